// round 14
// baseline (speedup 1.0000x reference)
#include <cuda_runtime.h>
#include <cuda_fp16.h>
#include <math_constants.h>

#define BATCH 1024
#define NGENE 8192
#define NSETS 2048
#define MAX_TOTAL 262144   // >= 2048 * 120

// Scratch (static device globals — no runtime allocation)
__device__ __half g_GT[NGENE * BATCH];    // transposed features, fp16, 16.8 MB
__device__ int2   g_pair[MAX_TOTAL];      // {gene byte offset, weight bits}, 2 MB
__device__ int    g_off[NSETS + 1];       // segment start offsets

// ---------------------------------------------------------------------------
// Warp-cooperative lower_bound on sorted seg: 32-ary search, 3 ballot rounds
// + 1 linear round = 4 dependent loads (vs 17 for serial binary search).
// Invariant: result in [lo, lo+len]; final popc covers the inclusive end.
// ---------------------------------------------------------------------------
__device__ __forceinline__ int warp_lb(const int* __restrict__ seg, int total,
                                       int key, int lane) {
    int lo = 0, len = total;
    while (len > 32) {
        int step = (len + 31) >> 5;
        int idx = lo + lane * step;
        int v = (idx < total) ? __ldg(seg + idx) : 0x7fffffff;
        unsigned m = __ballot_sync(0xFFFFFFFFu, v < key);
        if (m) lo += (31 - __clz(m)) * step;
        len = step;
    }
    int idx = lo + lane;
    int v = (lane < len && idx < total) ? __ldg(seg + idx) : 0x7fffffff;
    unsigned m = __ballot_sync(0xFFFFFFFFu, v < key);
    return lo + __popc(m);
}

// ---------------------------------------------------------------------------
// K1 (fused): heterogeneous grid.
//   blocks [0, 256)       : warp-per-segment softmax -> g_pair, g_off
//                           (bounds via warp-cooperative search; no
//                            separate k_offsets kernel needed)
//   blocks [256, 256+8192): 32x32 transpose tiles  G f32 -> GT f16
// The searches' latency hides under the DRAM-bound transpose.
// blockDim (32,8).
// ---------------------------------------------------------------------------
__global__ void k_prep(const float* __restrict__ G,
                       const float* __restrict__ logits,
                       const int* __restrict__ fidx,
                       const int* __restrict__ seg, int total) {
    int bid = blockIdx.x;
    if (bid < 256) {
        // ---- softmax part ----
        int tid  = threadIdx.y * 32 + threadIdx.x;
        int warp_id = bid * 8 + (tid >> 5);
        int lane = tid & 31;

        int beg = warp_lb(seg, total, warp_id, lane);
        int end = warp_lb(seg, total, warp_id + 1, lane);

        if (lane == 0) {
            g_off[warp_id] = beg;
            if (warp_id == NSETS - 1) g_off[NSETS] = total;
        }

        float m = -CUDART_INF_F;
        for (int p = beg + lane; p < end; p += 32) m = fmaxf(m, logits[p]);
        #pragma unroll
        for (int o = 16; o; o >>= 1) m = fmaxf(m, __shfl_xor_sync(0xFFFFFFFFu, m, o));

        float sum = 0.0f;
        for (int p = beg + lane; p < end; p += 32) sum += __expf(logits[p] - m);
        #pragma unroll
        for (int o = 16; o; o >>= 1) sum += __shfl_xor_sync(0xFFFFFFFFu, sum, o);

        float inv = (sum > 0.0f) ? (1.0f / sum) : 0.0f;
        for (int p = beg + lane; p < end; p += 32) {
            float w = __expf(logits[p] - m) * inv;
            g_pair[p] = make_int2(fidx[p] * (BATCH * 2), __float_as_int(w));
        }
    } else {
        // ---- transpose part ----
        int tb = bid - 256;
        __shared__ float tile[32][33];
        int gx = (tb & 255) * 32;   // gene base   (NGENE/32 = 256)
        int by = (tb >> 8) * 32;    // batch base  (BATCH/32 = 32)
        int x = gx + threadIdx.x;
        #pragma unroll
        for (int j = 0; j < 32; j += 8)
            tile[threadIdx.y + j][threadIdx.x] = G[(by + threadIdx.y + j) * NGENE + x];
        __syncthreads();
        #pragma unroll
        for (int j = 0; j < 32; j += 8)
            g_GT[(gx + threadIdx.y + j) * BATCH + by + threadIdx.x] =
                __float2half_rn(tile[threadIdx.x][threadIdx.y + j]);
    }
}

// ---------------------------------------------------------------------------
// K2: aggregation, 2048-block geometry (the only shape that reached
// issue=61%): grid = (NSETS/8 = 256, BATCH/128 = 8). Warp w owns set s0+w
// over batch rows b0..b0+127; thread = 4 rows via one LDG.64 (uint2) per
// edge -> warp gather = 256B, same memory shape as round-5's 31.6us kernel,
// plus direct coalesced 32B output stores (no staging kernel).
// ---------------------------------------------------------------------------
__global__ __launch_bounds__(256) void k_agg(float* __restrict__ out) {
    int t    = threadIdx.x;
    int warp = t >> 5;
    int lane = t & 31;
    int s0   = blockIdx.x * 8;
    int b0   = blockIdx.y * 128;
    int s    = s0 + warp;

    int beg = g_off[s];
    int n   = g_off[s + 1] - beg;
    if (n > 128) n = 128;             // structural: n <= 120

    // Thread covers rows b0 + lane*4 .. +3  (8 bytes of a GT row)
    const char* gt = reinterpret_cast<const char*>(g_GT) + b0 * 2 + lane * 8;
    const int2* pr = g_pair + beg;

    float4 acc = make_float4(0.f, 0.f, 0.f, 0.f);

    int i = 0;
    for (; i + 8 <= n; i += 8) {
        int2 p[8];
        #pragma unroll
        for (int k = 0; k < 8; k++) p[k] = pr[i + k];
        uint2 u[8];
        #pragma unroll
        for (int k = 0; k < 8; k++)
            u[k] = *reinterpret_cast<const uint2*>(gt + p[k].x);
        #pragma unroll
        for (int k = 0; k < 8; k++) {
            float w = __int_as_float(p[k].y);
            float2 v0 = __half22float2(*reinterpret_cast<const __half2*>(&u[k].x));
            float2 v1 = __half22float2(*reinterpret_cast<const __half2*>(&u[k].y));
            acc.x += w * v0.x;
            acc.y += w * v0.y;
            acc.z += w * v1.x;
            acc.w += w * v1.y;
        }
    }
    for (; i < n; i++) {
        int2 p = pr[i];
        uint2 u = *reinterpret_cast<const uint2*>(gt + p.x);
        float w = __int_as_float(p.y);
        float2 v0 = __half22float2(*reinterpret_cast<const __half2*>(&u.x));
        float2 v1 = __half22float2(*reinterpret_cast<const __half2*>(&u.y));
        acc.x += w * v0.x;
        acc.y += w * v0.y;
        acc.z += w * v1.x;
        acc.w += w * v1.y;
    }

    // Stage tile: buf[set][local batch row 0..127]
    __shared__ float buf[8][128];
    *reinterpret_cast<float4*>(&buf[warp][lane * 4]) = acc;
    __syncthreads();

    // Coalesced output: threads 0..127 write out[b0+t][s0..s0+7] (32B)
    if (t < 128) {
        float4 o0, o1;
        o0.x = buf[0][t]; o0.y = buf[1][t]; o0.z = buf[2][t]; o0.w = buf[3][t];
        o1.x = buf[4][t]; o1.y = buf[5][t]; o1.z = buf[6][t]; o1.w = buf[7][t];
        float* dst = out + (size_t)(b0 + t) * NSETS + s0;
        *reinterpret_cast<float4*>(dst)     = o0;
        *reinterpret_cast<float4*>(dst + 4) = o1;
    }
}

// ---------------------------------------------------------------------------
// Launcher (graph-capturable: kernel launches only, default stream ordering)
// ---------------------------------------------------------------------------
extern "C" void kernel_launch(void* const* d_in, const int* in_sizes, int n_in,
                              void* d_out, int out_size) {
    const float* G      = (const float*)d_in[0];
    const float* logits = (const float*)d_in[1];
    const int*   fidx   = (const int*)d_in[2];
    const int*   seg    = (const int*)d_in[3];
    float*       out    = (float*)d_out;
    int total = in_sizes[1];

    k_prep<<<256 + (NGENE / 32) * (BATCH / 32), dim3(32, 8)>>>(G, logits, fidx, seg, total);
    k_agg<<<dim3(NSETS / 8, BATCH / 128), 256>>>(out);
}

// round 15
// speedup vs baseline: 1.0855x; 1.0855x over previous
#include <cuda_runtime.h>
#include <cuda_fp16.h>
#include <math_constants.h>

#define BATCH 1024
#define NGENE 8192
#define NSETS 2048
#define MAX_TOTAL 262144   // >= 2048 * 120

// Scratch (static device globals — no runtime allocation)
__device__ __half g_GT[NGENE * BATCH];    // transposed features, fp16, 16.8 MB
__device__ int2   g_pair[MAX_TOTAL];      // {gene byte offset, weight bits}, 2 MB
__device__ int    g_off[NSETS + 1];       // segment start offsets

// ---------------------------------------------------------------------------
// Warp-cooperative lower_bound on sorted seg: 32-ary search, 3 ballot rounds
// + 1 linear round = 4 dependent loads.
// ---------------------------------------------------------------------------
__device__ __forceinline__ int warp_lb(const int* __restrict__ seg, int total,
                                       int key, int lane) {
    int lo = 0, len = total;
    while (len > 32) {
        int step = (len + 31) >> 5;
        int idx = lo + lane * step;
        int v = (idx < total) ? __ldg(seg + idx) : 0x7fffffff;
        unsigned m = __ballot_sync(0xFFFFFFFFu, v < key);
        if (m) lo += (31 - __clz(m)) * step;
        len = step;
    }
    int idx = lo + lane;
    int v = (lane < len && idx < total) ? __ldg(seg + idx) : 0x7fffffff;
    unsigned m = __ballot_sync(0xFFFFFFFFu, v < key);
    return lo + __popc(m);
}

// ---------------------------------------------------------------------------
// K1 (fused, round-14 proven ~8.0us): heterogeneous grid.
//   blocks [0, 256)       : warp-per-segment softmax -> g_pair, g_off
//   blocks [256, 256+8192): 32x32 transpose tiles  G f32 -> GT f16
// blockDim (32,8).
// ---------------------------------------------------------------------------
__global__ void k_prep(const float* __restrict__ G,
                       const float* __restrict__ logits,
                       const int* __restrict__ fidx,
                       const int* __restrict__ seg, int total) {
    int bid = blockIdx.x;
    if (bid < 256) {
        // ---- softmax part ----
        int tid  = threadIdx.y * 32 + threadIdx.x;
        int warp_id = bid * 8 + (tid >> 5);
        int lane = tid & 31;

        int beg = warp_lb(seg, total, warp_id, lane);
        int end = warp_lb(seg, total, warp_id + 1, lane);

        if (lane == 0) {
            g_off[warp_id] = beg;
            if (warp_id == NSETS - 1) g_off[NSETS] = total;
        }

        float m = -CUDART_INF_F;
        for (int p = beg + lane; p < end; p += 32) m = fmaxf(m, logits[p]);
        #pragma unroll
        for (int o = 16; o; o >>= 1) m = fmaxf(m, __shfl_xor_sync(0xFFFFFFFFu, m, o));

        float sum = 0.0f;
        for (int p = beg + lane; p < end; p += 32) sum += __expf(logits[p] - m);
        #pragma unroll
        for (int o = 16; o; o >>= 1) sum += __shfl_xor_sync(0xFFFFFFFFu, sum, o);

        float inv = (sum > 0.0f) ? (1.0f / sum) : 0.0f;
        for (int p = beg + lane; p < end; p += 32) {
            float w = __expf(logits[p] - m) * inv;
            g_pair[p] = make_int2(fidx[p] * (BATCH * 2), __float_as_int(w));
        }
    } else {
        // ---- transpose part ----
        int tb = bid - 256;
        __shared__ float tile[32][33];
        int gx = (tb & 255) * 32;   // gene base   (NGENE/32 = 256)
        int by = (tb >> 8) * 32;    // batch base  (BATCH/32 = 32)
        int x = gx + threadIdx.x;
        #pragma unroll
        for (int j = 0; j < 32; j += 8)
            tile[threadIdx.y + j][threadIdx.x] = G[(by + threadIdx.y + j) * NGENE + x];
        __syncthreads();
        #pragma unroll
        for (int j = 0; j < 32; j += 8)
            g_GT[(gx + threadIdx.y + j) * BATCH + by + threadIdx.x] =
                __float2half_rn(tile[threadIdx.x][threadIdx.y + j]);
    }
}

// ---------------------------------------------------------------------------
// K2: 2D-tiled aggregation writing out directly (round-11 exact: 33.5us,
// the measured optimum of the k_agg family).
// grid = (NSETS/8 = 256, BATCH/256 = 4), block = 256 threads.
// Warp w owns set s0+w over batch rows b0..b0+255; thread = 8 rows (uint4).
// Result tile (8 sets x 256 rows) staged in 8KB smem, then written as
// fully-coalesced 32B chunks: out[b0+t][s0..s0+7].
// ---------------------------------------------------------------------------
__device__ __forceinline__ void fma8(float4& a0, float4& a1, uint4 u, float w) {
    float2 v;
    v = __half22float2(*reinterpret_cast<const __half2*>(&u.x));
    a0.x += w * v.x;  a0.y += w * v.y;
    v = __half22float2(*reinterpret_cast<const __half2*>(&u.y));
    a0.z += w * v.x;  a0.w += w * v.y;
    v = __half22float2(*reinterpret_cast<const __half2*>(&u.z));
    a1.x += w * v.x;  a1.y += w * v.y;
    v = __half22float2(*reinterpret_cast<const __half2*>(&u.w));
    a1.z += w * v.x;  a1.w += w * v.y;
}

__global__ __launch_bounds__(256) void k_agg(float* __restrict__ out) {
    int t    = threadIdx.x;
    int warp = t >> 5;
    int lane = t & 31;
    int s0   = blockIdx.x * 8;
    int b0   = blockIdx.y * 256;
    int s    = s0 + warp;

    int beg = g_off[s];
    int n   = g_off[s + 1] - beg;
    if (n > 128) n = 128;             // structural: n <= 120

    const char* gt = reinterpret_cast<const char*>(g_GT) + b0 * 2 + lane * 16;
    const int2* pr = g_pair + beg;

    float4 a0 = make_float4(0.f, 0.f, 0.f, 0.f);
    float4 a1 = make_float4(0.f, 0.f, 0.f, 0.f);

    int i = 0;
    for (; i + 8 <= n; i += 8) {
        int2 p[8];
        #pragma unroll
        for (int k = 0; k < 8; k++) p[k] = pr[i + k];
        uint4 u[8];
        #pragma unroll
        for (int k = 0; k < 8; k++)
            u[k] = *reinterpret_cast<const uint4*>(gt + p[k].x);
        #pragma unroll
        for (int k = 0; k < 8; k++)
            fma8(a0, a1, u[k], __int_as_float(p[k].y));
    }
    for (; i < n; i++) {
        int2 p = pr[i];
        uint4 u = *reinterpret_cast<const uint4*>(gt + p.x);
        fma8(a0, a1, u, __int_as_float(p.y));
    }

    // Stage tile: buf[set][local batch row]; thread's rows are 8*lane..8*lane+7
    __shared__ float buf[8][256];
    *reinterpret_cast<float4*>(&buf[warp][lane * 8 + 0]) = a0;
    *reinterpret_cast<float4*>(&buf[warp][lane * 8 + 4]) = a1;
    __syncthreads();

    // Coalesced output: thread t writes out[b0+t][s0..s0+7] (32B, sector-full)
    float4 o0, o1;
    o0.x = buf[0][t]; o0.y = buf[1][t]; o0.z = buf[2][t]; o0.w = buf[3][t];
    o1.x = buf[4][t]; o1.y = buf[5][t]; o1.z = buf[6][t]; o1.w = buf[7][t];
    float* dst = out + (size_t)(b0 + t) * NSETS + s0;
    *reinterpret_cast<float4*>(dst)     = o0;
    *reinterpret_cast<float4*>(dst + 4) = o1;
}

// ---------------------------------------------------------------------------
// Launcher (graph-capturable: kernel launches only, default stream ordering)
// ---------------------------------------------------------------------------
extern "C" void kernel_launch(void* const* d_in, const int* in_sizes, int n_in,
                              void* d_out, int out_size) {
    const float* G      = (const float*)d_in[0];
    const float* logits = (const float*)d_in[1];
    const int*   fidx   = (const int*)d_in[2];
    const int*   seg    = (const int*)d_in[3];
    float*       out    = (float*)d_out;
    int total = in_sizes[1];

    k_prep<<<256 + (NGENE / 32) * (BATCH / 32), dim3(32, 8)>>>(G, logits, fidx, seg, total);
    k_agg<<<dim3(NSETS / 8, BATCH / 256), 256>>>(out);
}

// round 16
// speedup vs baseline: 1.1491x; 1.0585x over previous
#include <cuda_runtime.h>
#include <cuda_fp16.h>
#include <math_constants.h>

#define BATCH 1024
#define NGENE 8192
#define NSETS 2048
#define MAX_TOTAL 262144   // >= 2048 * 120

// Scratch (static device globals — no runtime allocation)
__device__ __half g_GT[NGENE * BATCH];    // transposed features, fp16, 16.8 MB
__device__ int2   g_pair[MAX_TOTAL];      // {gene byte offset, weight bits}, 2 MB
__device__ int    g_off[NSETS + 1];       // segment start offsets

// ---------------------------------------------------------------------------
// Warp-cooperative lower_bound on sorted seg: 32-ary search, 3 ballot rounds
// + 1 linear round = 4 dependent loads.
// ---------------------------------------------------------------------------
__device__ __forceinline__ int warp_lb(const int* __restrict__ seg, int total,
                                       int key, int lane) {
    int lo = 0, len = total;
    while (len > 32) {
        int step = (len + 31) >> 5;
        int idx = lo + lane * step;
        int v = (idx < total) ? __ldg(seg + idx) : 0x7fffffff;
        unsigned m = __ballot_sync(0xFFFFFFFFu, v < key);
        if (m) lo += (31 - __clz(m)) * step;
        len = step;
    }
    int idx = lo + lane;
    int v = (lane < len && idx < total) ? __ldg(seg + idx) : 0x7fffffff;
    unsigned m = __ballot_sync(0xFFFFFFFFu, v < key);
    return lo + __popc(m);
}

// ---------------------------------------------------------------------------
// K1 (fused, proven ~9.6us incl. gap): heterogeneous grid.
//   blocks [0, 256)       : warp-per-segment softmax -> g_pair, g_off
//   blocks [256, 256+8192): 32x32 transpose tiles  G f32 -> GT f16
// blockDim (32,8).
// ---------------------------------------------------------------------------
__global__ void k_prep(const float* __restrict__ G,
                       const float* __restrict__ logits,
                       const int* __restrict__ fidx,
                       const int* __restrict__ seg, int total) {
    int bid = blockIdx.x;
    if (bid < 256) {
        // ---- softmax part ----
        int tid  = threadIdx.y * 32 + threadIdx.x;
        int warp_id = bid * 8 + (tid >> 5);
        int lane = tid & 31;

        int beg = warp_lb(seg, total, warp_id, lane);
        int end = warp_lb(seg, total, warp_id + 1, lane);

        if (lane == 0) {
            g_off[warp_id] = beg;
            if (warp_id == NSETS - 1) g_off[NSETS] = total;
        }

        float m = -CUDART_INF_F;
        for (int p = beg + lane; p < end; p += 32) m = fmaxf(m, logits[p]);
        #pragma unroll
        for (int o = 16; o; o >>= 1) m = fmaxf(m, __shfl_xor_sync(0xFFFFFFFFu, m, o));

        float sum = 0.0f;
        for (int p = beg + lane; p < end; p += 32) sum += __expf(logits[p] - m);
        #pragma unroll
        for (int o = 16; o; o >>= 1) sum += __shfl_xor_sync(0xFFFFFFFFu, sum, o);

        float inv = (sum > 0.0f) ? (1.0f / sum) : 0.0f;
        for (int p = beg + lane; p < end; p += 32) {
            float w = __expf(logits[p] - m) * inv;
            g_pair[p] = make_int2(fidx[p] * (BATCH * 2), __float_as_int(w));
        }
    } else {
        // ---- transpose part ----
        int tb = bid - 256;
        __shared__ float tile[32][33];
        int gx = (tb & 255) * 32;   // gene base   (NGENE/32 = 256)
        int by = (tb >> 8) * 32;    // batch base  (BATCH/32 = 32)
        int x = gx + threadIdx.x;
        #pragma unroll
        for (int j = 0; j < 32; j += 8)
            tile[threadIdx.y + j][threadIdx.x] = G[(by + threadIdx.y + j) * NGENE + x];
        __syncthreads();
        #pragma unroll
        for (int j = 0; j < 32; j += 8)
            g_GT[(gx + threadIdx.y + j) * BATCH + by + threadIdx.x] =
                __float2half_rn(tile[threadIdx.x][threadIdx.y + j]);
    }
}

// ---------------------------------------------------------------------------
// K2: 2D-tiled aggregation writing out directly. Identical work shape to
// the measured-best 33.3us kernel, but __launch_bounds__(256, 4) raises the
// register budget to 64/thread so the 8-wide descriptor+gather batch can
// actually stay live (previous builds clamped to 32 regs and re-serialized).
// grid = (NSETS/8 = 256, BATCH/256 = 4), block = 256 threads.
// ---------------------------------------------------------------------------
__device__ __forceinline__ void fma8(float4& a0, float4& a1, uint4 u, float w) {
    float2 v;
    v = __half22float2(*reinterpret_cast<const __half2*>(&u.x));
    a0.x += w * v.x;  a0.y += w * v.y;
    v = __half22float2(*reinterpret_cast<const __half2*>(&u.y));
    a0.z += w * v.x;  a0.w += w * v.y;
    v = __half22float2(*reinterpret_cast<const __half2*>(&u.z));
    a1.x += w * v.x;  a1.y += w * v.y;
    v = __half22float2(*reinterpret_cast<const __half2*>(&u.w));
    a1.z += w * v.x;  a1.w += w * v.y;
}

__global__ __launch_bounds__(256, 4) void k_agg(float* __restrict__ out) {
    int t    = threadIdx.x;
    int warp = t >> 5;
    int lane = t & 31;
    int s0   = blockIdx.x * 8;
    int b0   = blockIdx.y * 256;
    int s    = s0 + warp;

    int beg = g_off[s];
    int n   = g_off[s + 1] - beg;
    if (n > 128) n = 128;             // structural: n <= 120

    const char* gt = reinterpret_cast<const char*>(g_GT) + b0 * 2 + lane * 16;
    const int2* pr = g_pair + beg;

    float4 a0 = make_float4(0.f, 0.f, 0.f, 0.f);
    float4 a1 = make_float4(0.f, 0.f, 0.f, 0.f);

    int i = 0;
    for (; i + 8 <= n; i += 8) {
        int2 p[8];
        #pragma unroll
        for (int k = 0; k < 8; k++) p[k] = pr[i + k];
        uint4 u[8];
        #pragma unroll
        for (int k = 0; k < 8; k++)
            u[k] = *reinterpret_cast<const uint4*>(gt + p[k].x);
        #pragma unroll
        for (int k = 0; k < 8; k++)
            fma8(a0, a1, u[k], __int_as_float(p[k].y));
    }
    for (; i < n; i++) {
        int2 p = pr[i];
        uint4 u = *reinterpret_cast<const uint4*>(gt + p.x);
        fma8(a0, a1, u, __int_as_float(p.y));
    }

    // Stage tile: buf[set][local batch row]; thread's rows are 8*lane..8*lane+7
    __shared__ float buf[8][256];
    *reinterpret_cast<float4*>(&buf[warp][lane * 8 + 0]) = a0;
    *reinterpret_cast<float4*>(&buf[warp][lane * 8 + 4]) = a1;
    __syncthreads();

    // Coalesced output: thread t writes out[b0+t][s0..s0+7] (32B, sector-full)
    float4 o0, o1;
    o0.x = buf[0][t]; o0.y = buf[1][t]; o0.z = buf[2][t]; o0.w = buf[3][t];
    o1.x = buf[4][t]; o1.y = buf[5][t]; o1.z = buf[6][t]; o1.w = buf[7][t];
    float* dst = out + (size_t)(b0 + t) * NSETS + s0;
    *reinterpret_cast<float4*>(dst)     = o0;
    *reinterpret_cast<float4*>(dst + 4) = o1;
}

// ---------------------------------------------------------------------------
// Launcher (graph-capturable: kernel launches only, default stream ordering)
// ---------------------------------------------------------------------------
extern "C" void kernel_launch(void* const* d_in, const int* in_sizes, int n_in,
                              void* d_out, int out_size) {
    const float* G      = (const float*)d_in[0];
    const float* logits = (const float*)d_in[1];
    const int*   fidx   = (const int*)d_in[2];
    const int*   seg    = (const int*)d_in[3];
    float*       out    = (float*)d_out;
    int total = in_sizes[1];

    k_prep<<<256 + (NGENE / 32) * (BATCH / 32), dim3(32, 8)>>>(G, logits, fidx, seg, total);
    k_agg<<<dim3(NSETS / 8, BATCH / 256), 256>>>(out);
}